// round 8
// baseline (speedup 1.0000x reference)
#include <cuda_runtime.h>
#include <math.h>
#include <stdint.h>

#define BB 8
#define LL 4096
#define CIN 96
#define DI 192
#define KK 4
#define RR 6
#define NN 16
#define KRR 24
#define NCH 64
#define TT 64
#define CPROJ 38
#define KC 152   // KK*CPROJ

// scratch (static device globals; no allocation)
__device__ float  d_z [BB*LL*DI];
__device__ float  d_xi[BB*LL*DI];
__device__ float  d_BC[BB*LL*KK*32];          // per (b,l,k): B[0..15], C[16..31]
__device__ float2 d_dtdk[BB*LL*KK*RR];        // (dt, decay)
__device__ float  d_ys[BB*LL*KK*RR*32];
__device__ float  d_P [BB*KRR*LL];            // cumulative within-chunk decay
__device__ float  d_h [BB*KRR*NCH*32*NN];     // chunk-end states (from A)
__device__ float  d_h0[BB*KRR*NCH*32*NN];     // chunk-start states (from B)

__device__ __forceinline__ int tau_idx(int l) { return ((l & 63) << 6) | (l >> 6); }
__device__ __forceinline__ int sigma_k(int k, int l) {
    int t = (k & 1) ? tau_idx(l) : l;
    return (k >= 2) ? (4095 - t) : t;
}
__device__ __forceinline__ uint32_t f2tf32(float v) {
    uint32_t o; asm("cvt.rna.tf32.f32 %0, %1;" : "=r"(o) : "f"(v)); return o;
}

// ---------- K1: z = x @ w_in via mma.sync tf32, M=128 N=192 K=96 per CTA ----------
#define K1_SAK 100
#define K1_SBK 100
#define K1_SA_FLOATS (128 * K1_SAK)
#define K1_SB_FLOATS (192 * K1_SBK)
#define K1_SMEM_BYTES ((K1_SA_FLOATS + K1_SB_FLOATS) * 4)

__global__ __launch_bounds__(256) void k1_mma(const float* __restrict__ x,
                                              const float* __restrict__ w_in) {
    extern __shared__ __align__(16) uint32_t smem1[];
    uint32_t* sA = smem1;                   // [128][K1_SAK]
    uint32_t* sB = smem1 + K1_SA_FLOATS;    // [192][K1_SBK]  (B[n][k], transposed w_in)

    int t = threadIdx.x;                    // 256
    int wid = t >> 5, lane = t & 31;
    int g = lane >> 2, tg = lane & 3;
    int pix0 = blockIdx.x * 128;

    // Stage A: x[pix0..pix0+127][0..95] -> tf32
    {
        const float4* src = reinterpret_cast<const float4*>(x + pix0 * CIN);
        for (int idx = t; idx < 128 * 24; idx += 256) {
            int row = idx / 24, c4 = idx % 24;
            float4 v = src[idx];
            uint4 tv = make_uint4(f2tf32(v.x), f2tf32(v.y), f2tf32(v.z), f2tf32(v.w));
            *reinterpret_cast<uint4*>(&sA[row * K1_SAK + c4 * 4]) = tv;
        }
    }
    // Stage B: w_in[k][n] -> sB[n][k] tf32 (transpose)
    {
        for (int idx = t; idx < CIN * 48; idx += 256) {
            int k = idx / 48, n4 = idx % 48;
            float4 v = *reinterpret_cast<const float4*>(&w_in[k * DI + n4 * 4]);
            sB[(n4 * 4 + 0) * K1_SBK + k] = f2tf32(v.x);
            sB[(n4 * 4 + 1) * K1_SBK + k] = f2tf32(v.y);
            sB[(n4 * 4 + 2) * K1_SBK + k] = f2tf32(v.z);
            sB[(n4 * 4 + 3) * K1_SBK + k] = f2tf32(v.w);
        }
    }
    __syncthreads();

    int m0 = wid * 16;
    int row0 = m0 + g, row1 = m0 + g + 8;
    float cacc[24][4];
#pragma unroll
    for (int nt = 0; nt < 24; nt++)
#pragma unroll
        for (int j = 0; j < 4; j++) cacc[nt][j] = 0.f;

    const uint32_t* pa0 = &sA[row0 * K1_SAK + tg];
    const uint32_t* pa1 = &sA[row1 * K1_SAK + tg];
#pragma unroll
    for (int k0 = 0; k0 < CIN; k0 += 8) {
        uint32_t a0 = pa0[k0], a2 = pa0[k0 + 4];
        uint32_t a1 = pa1[k0], a3 = pa1[k0 + 4];
        const uint32_t* pb = &sB[g * K1_SBK + k0 + tg];
#pragma unroll
        for (int nt = 0; nt < 24; nt++) {
            uint32_t b0 = pb[nt * 8 * K1_SBK];
            uint32_t b1 = pb[nt * 8 * K1_SBK + 4];
            asm volatile(
                "mma.sync.aligned.m16n8k8.row.col.f32.tf32.tf32.f32 "
                "{%0,%1,%2,%3}, {%4,%5,%6,%7}, {%8,%9}, {%0,%1,%2,%3};"
                : "+f"(cacc[nt][0]), "+f"(cacc[nt][1]), "+f"(cacc[nt][2]), "+f"(cacc[nt][3])
                : "r"(a0), "r"(a1), "r"(a2), "r"(a3), "r"(b0), "r"(b1));
        }
    }

#pragma unroll
    for (int nt = 0; nt < 24; nt++) {
        int n = nt * 8 + 2 * tg;
        *reinterpret_cast<float2*>(&d_z[(pix0 + row0) * DI + n]) =
            make_float2(cacc[nt][0], cacc[nt][1]);
        *reinterpret_cast<float2*>(&d_z[(pix0 + row1) * DI + n]) =
            make_float2(cacc[nt][2], cacc[nt][3]);
    }
}

// ---------- K2: depthwise 3x3 conv + bias + silu ----------
__global__ void k2_conv(const float* __restrict__ wc, const float* __restrict__ bcv) {
    int c = threadIdx.x;               // 0..191
    int seg = blockIdx.x;              // 4096
    int b = seg >> 9;
    int h = (seg >> 3) & 63;
    int w0 = (seg & 7) << 3;
    float wreg[9];
#pragma unroll
    for (int i = 0; i < 9; i++) wreg[i] = wc[i * DI + c];
    float row[3][10];
#pragma unroll
    for (int dh = 0; dh < 3; dh++) {
        int hh = h + dh - 1;
        bool hok = (hh >= 0 && hh < 64);
#pragma unroll
        for (int dw = 0; dw < 10; dw++) {
            int ww = w0 + dw - 1;
            row[dh][dw] = (hok && ww >= 0 && ww < 64)
                ? d_z[(((b << 12) + (hh << 6) + ww)) * DI + c] : 0.f;
        }
    }
    float bias = bcv[c];
#pragma unroll
    for (int q = 0; q < 8; q++) {
        float acc = bias;
#pragma unroll
        for (int dh = 0; dh < 3; dh++)
#pragma unroll
            for (int dw = 0; dw < 3; dw++)
                acc = fmaf(row[dh][q + dw], wreg[dh * 3 + dw], acc);
        int pix = (b << 12) + (h << 6) + w0 + q;
        d_xi[pix * DI + c] = acc / (1.f + expf(-acc));
    }
}

// ---------- K3: projection GEMM via mma.sync tf32, M=128 N=152 K=192 per CTA ----------
#define SAK 196
#define SBK 196
#define SA_FLOATS (128 * SAK)
#define SB_FLOATS (152 * SBK)
#define K3_SMEM_BYTES ((SA_FLOATS + SB_FLOATS + 64) * 4)

__global__ __launch_bounds__(256) void k3_mma(const float* __restrict__ xpw,
                                              const float* __restrict__ Alogs,
                                              const float* __restrict__ dtb) {
    extern __shared__ __align__(16) uint32_t smem[];
    uint32_t* sA = smem;
    uint32_t* sB = smem + SA_FLOATS;
    float* sAk  = reinterpret_cast<float*>(smem + SA_FLOATS + SB_FLOATS);
    float* sdtb = sAk + KRR;

    int t = threadIdx.x;                 // 256
    int wid = t >> 5, lane = t & 31;
    int g = lane >> 2, tg = lane & 3;

    int pix0 = blockIdx.x * 128;
    int b = pix0 >> 12;
    int l0 = pix0 & 4095;

    if (t < KRR) { sAk[t] = -expf(Alogs[t]); sdtb[t] = dtb[t]; }

    {
        const float4* src = reinterpret_cast<const float4*>(d_xi + pix0 * DI);
        for (int idx = t; idx < 128 * 48; idx += 256) {
            int row = idx / 48, c4 = idx % 48;
            float4 v = src[idx];
            uint4 tv = make_uint4(f2tf32(v.x), f2tf32(v.y), f2tf32(v.z), f2tf32(v.w));
            *reinterpret_cast<uint4*>(&sA[row * SAK + c4 * 4]) = tv;
        }
    }
    {
        const float4* src = reinterpret_cast<const float4*>(xpw);
        for (int idx = t; idx < 152 * 48; idx += 256) {
            int n = idx / 48, c4 = idx % 48;
            float4 v = src[idx];
            uint4 tv = make_uint4(f2tf32(v.x), f2tf32(v.y), f2tf32(v.z), f2tf32(v.w));
            *reinterpret_cast<uint4*>(&sB[n * SBK + c4 * 4]) = tv;
        }
    }
    __syncthreads();

    int m0 = wid * 16;
    int row0 = m0 + g, row1 = m0 + g + 8;
    float cacc[19][4];
#pragma unroll
    for (int nt = 0; nt < 19; nt++)
#pragma unroll
        for (int j = 0; j < 4; j++) cacc[nt][j] = 0.f;

    const uint32_t* pa0 = &sA[row0 * SAK + tg];
    const uint32_t* pa1 = &sA[row1 * SAK + tg];
#pragma unroll 4
    for (int k0 = 0; k0 < 192; k0 += 8) {
        uint32_t a0 = pa0[k0], a2 = pa0[k0 + 4];
        uint32_t a1 = pa1[k0], a3 = pa1[k0 + 4];
        const uint32_t* pb = &sB[g * SBK + k0 + tg];
#pragma unroll
        for (int nt = 0; nt < 19; nt++) {
            uint32_t b0 = pb[nt * 8 * SBK];
            uint32_t b1 = pb[nt * 8 * SBK + 4];
            asm volatile(
                "mma.sync.aligned.m16n8k8.row.col.f32.tf32.tf32.f32 "
                "{%0,%1,%2,%3}, {%4,%5,%6,%7}, {%8,%9}, {%0,%1,%2,%3};"
                : "+f"(cacc[nt][0]), "+f"(cacc[nt][1]), "+f"(cacc[nt][2]), "+f"(cacc[nt][3])
                : "r"(a0), "r"(a1), "r"(a2), "r"(a3), "r"(b0), "r"(b1));
        }
    }

#pragma unroll
    for (int nt = 0; nt < 19; nt++) {
        int kc = nt * 8 + 2 * tg;
        int k = kc / CPROJ;
        int c = kc - k * CPROJ;
#pragma unroll
        for (int hh = 0; hh < 2; hh++) {
            int row = (hh == 0) ? row0 : row1;
            float v0 = cacc[nt][2 * hh + 0], v1 = cacc[nt][2 * hh + 1];
            int pos = sigma_k(k, l0 + row);
            if (c < RR) {
                float A0 = sAk[k * RR + c],     tb0 = sdtb[k * RR + c];
                float A1 = sAk[k * RR + c + 1], tb1 = sdtb[k * RR + c + 1];
                float x0 = v0 + tb0, x1 = v1 + tb1;
                float dt0 = (x0 > 20.f) ? x0 : log1pf(expf(x0));
                float dt1 = (x1 > 20.f) ? x1 : log1pf(expf(x1));
                float4 w = make_float4(dt0, expf(dt0 * A0), dt1, expf(dt1 * A1));
                *reinterpret_cast<float4*>(&d_dtdk[((b * LL + pos) * KK + k) * RR + c]) = w;
            } else {
                *reinterpret_cast<float2*>(&d_BC[((b * LL + pos) * KK + k) * 32 + (c - RR)]) =
                    make_float2(v0, v1);
            }
        }
    }
}

// ---------- K4A: per-chunk local scan; quad-interleaved, split-y, tighter regs ----------
__global__ __launch_bounds__(192, 6) void k4_scanA(const float* __restrict__ Ds) {
    __shared__ __align__(16) float4 sBC[TT * 8];   // 8KB
    __shared__ float2 sdt[TT * RR];                // 3KB
    int bx = blockIdx.x;                 // 2048 = b(8) * k(4) * chunk(64)
    int chunk = bx & 63, k = (bx >> 6) & 3, b = bx >> 8;
    int t = threadIdx.x;
    int warp = t >> 5, lane = t & 31;
    int l0 = chunk * TT;

    const float4* bc4 = reinterpret_cast<const float4*>(d_BC);
    int g4 = ((b * LL + l0) * KK + k) * 8;
    for (int j = t; j < TT * 8; j += 192) {
        int s = j >> 3, w = j & 7;
        sBC[j] = bc4[g4 + s * KK * 8 + w];
    }
    int gd = ((b * LL + l0) * KK + k) * RR;
    for (int j = t; j < TT * RR; j += 192) {
        int s = j / RR, r = j % RR;
        sdt[j] = d_dtdk[gd + s * KK * RR + r];
    }
    __syncthreads();

    int r = warp;  // 0..5
    int sl = b * KRR + k * RR + r;
    float Dd = Ds[(k * RR + r) * 32 + lane];

    int ubase, ustride;
    if (k == 0)      { ubase = l0;        ustride = 1;   }
    else if (k == 1) { ubase = chunk;     ustride = 64;  }
    else if (k == 2) { ubase = 4095 - l0; ustride = -1;  }
    else             { ubase = 4095 - chunk; ustride = -64; }
    const float* up = d_xi + (b * LL + ubase) * DI + r * 32 + lane;
    int ustep = ustride * DI;

    float h[NN];
#pragma unroll
    for (int n = 0; n < NN; n++) h[n] = 0.f;
    float P = 1.f;
    int ysIdx = ((b * LL + l0) * KK + k) * 192 + r * 32 + lane;
    int pIdx  = sl * LL + l0;

#pragma unroll 2
    for (int s = 0; s < TT; s++) {
        float u = *up; up += ustep;
        float2 dd = sdt[s * RR + r];
        float xu = dd.x * u;
        float dk = dd.y;
        float y0, y1, y2, y3;
        {
            float4 bq = sBC[s * 8 + 0];
            h[0] = fmaf(dk, h[0], xu * bq.x);
            h[1] = fmaf(dk, h[1], xu * bq.y);
            h[2] = fmaf(dk, h[2], xu * bq.z);
            h[3] = fmaf(dk, h[3], xu * bq.w);
            float4 cq = sBC[s * 8 + 4];
            y0 = h[0] * cq.x;
            y0 = fmaf(h[1], cq.y, y0);
            y0 = fmaf(h[2], cq.z, y0);
            y0 = fmaf(h[3], cq.w, y0);
        }
        {
            float4 bq = sBC[s * 8 + 1];
            h[4] = fmaf(dk, h[4], xu * bq.x);
            h[5] = fmaf(dk, h[5], xu * bq.y);
            h[6] = fmaf(dk, h[6], xu * bq.z);
            h[7] = fmaf(dk, h[7], xu * bq.w);
            float4 cq = sBC[s * 8 + 5];
            y1 = h[4] * cq.x;
            y1 = fmaf(h[5], cq.y, y1);
            y1 = fmaf(h[6], cq.z, y1);
            y1 = fmaf(h[7], cq.w, y1);
        }
        {
            float4 bq = sBC[s * 8 + 2];
            h[8]  = fmaf(dk, h[8],  xu * bq.x);
            h[9]  = fmaf(dk, h[9],  xu * bq.y);
            h[10] = fmaf(dk, h[10], xu * bq.z);
            h[11] = fmaf(dk, h[11], xu * bq.w);
            float4 cq = sBC[s * 8 + 6];
            y2 = h[8] * cq.x;
            y2 = fmaf(h[9],  cq.y, y2);
            y2 = fmaf(h[10], cq.z, y2);
            y2 = fmaf(h[11], cq.w, y2);
        }
        {
            float4 bq = sBC[s * 8 + 3];
            h[12] = fmaf(dk, h[12], xu * bq.x);
            h[13] = fmaf(dk, h[13], xu * bq.y);
            h[14] = fmaf(dk, h[14], xu * bq.z);
            h[15] = fmaf(dk, h[15], xu * bq.w);
            float4 cq = sBC[s * 8 + 7];
            y3 = h[12] * cq.x;
            y3 = fmaf(h[13], cq.y, y3);
            y3 = fmaf(h[14], cq.z, y3);
            y3 = fmaf(h[15], cq.w, y3);
        }
        P *= dk;
        d_ys[ysIdx] = fmaf(u, Dd, (y0 + y1) + (y2 + y3));
        if (lane == 0) d_P[pIdx] = P;
        ysIdx += KK * 192; pIdx += 1;
    }
    float4* hp = reinterpret_cast<float4*>(d_h + ((sl * NCH + chunk) * 32 + lane) * NN);
    hp[0] = make_float4(h[0], h[1], h[2], h[3]);
    hp[1] = make_float4(h[4], h[5], h[6], h[7]);
    hp[2] = make_float4(h[8], h[9], h[10], h[11]);
    hp[3] = make_float4(h[12], h[13], h[14], h[15]);
}

// ---------- K4B: sequential carry across chunks ----------
__global__ void k4_scanB() {
    int wid = (blockIdx.x * blockDim.x + threadIdx.x) >> 5;  // 0..191
    int lane = threadIdx.x & 31;
    float h0[NN];
#pragma unroll
    for (int n = 0; n < NN; n++) h0[n] = 0.f;

    const float4* src = reinterpret_cast<const float4*>(d_h + ((wid * NCH) * 32 + lane) * NN);
    float4 a0 = src[0], a1 = src[1], a2 = src[2], a3 = src[3];
    float Dc = d_P[wid * LL + TT - 1];

    for (int c = 0; c < NCH; c++) {
        float4 n0, n1, n2, n3; float Dn = 0.f;
        if (c + 1 < NCH) {
            const float4* s2 = reinterpret_cast<const float4*>(
                d_h + ((wid * NCH + c + 1) * 32 + lane) * NN);
            n0 = s2[0]; n1 = s2[1]; n2 = s2[2]; n3 = s2[3];
            Dn = d_P[wid * LL + (c + 1) * TT + TT - 1];
        } else {
            n0 = n1 = n2 = n3 = make_float4(0.f, 0.f, 0.f, 0.f);
        }
        float4* dst = reinterpret_cast<float4*>(d_h0 + ((wid * NCH + c) * 32 + lane) * NN);
        dst[0] = make_float4(h0[0], h0[1], h0[2], h0[3]);
        dst[1] = make_float4(h0[4], h0[5], h0[6], h0[7]);
        dst[2] = make_float4(h0[8], h0[9], h0[10], h0[11]);
        dst[3] = make_float4(h0[12], h0[13], h0[14], h0[15]);
        float av[NN] = {a0.x,a0.y,a0.z,a0.w, a1.x,a1.y,a1.z,a1.w,
                        a2.x,a2.y,a2.z,a2.w, a3.x,a3.y,a3.z,a3.w};
#pragma unroll
        for (int n = 0; n < NN; n++) h0[n] = fmaf(Dc, h0[n], av[n]);
        a0 = n0; a1 = n1; a2 = n2; a3 = n3; Dc = Dn;
    }
}

// ---------- K4C: fixup ys += P_l * (h0 . C_l); quad split accumulators ----------
__global__ __launch_bounds__(192, 6) void k4_scanC() {
    __shared__ __align__(16) float4 sC[TT * 4];  // 4KB
    __shared__ float sP[RR * TT];                // 1.5KB
    int bx = blockIdx.x;
    int chunk = bx & 63, k = (bx >> 6) & 3, b = bx >> 8;
    int t = threadIdx.x;
    int warp = t >> 5, lane = t & 31;
    int l0 = chunk * TT;

    const float4* bc4 = reinterpret_cast<const float4*>(d_BC);
    int g4 = ((b * LL + l0) * KK + k) * 8;
    for (int j = t; j < TT * 4; j += 192) {
        int s = j >> 2, w = j & 3;
        sC[j] = bc4[g4 + s * KK * 8 + 4 + w];
    }
    for (int j = t; j < RR * TT; j += 192) {
        int r = j / TT, s = j % TT;
        sP[j] = d_P[(b * KRR + k * RR + r) * LL + l0 + s];
    }
    __syncthreads();

    int r = warp;
    int sl = b * KRR + k * RR + r;
    const float4* hp = reinterpret_cast<const float4*>(d_h0 + ((sl * NCH + chunk) * 32 + lane) * NN);
    float4 a0 = hp[0], a1 = hp[1], a2 = hp[2], a3 = hp[3];
    float h0[NN] = {a0.x,a0.y,a0.z,a0.w, a1.x,a1.y,a1.z,a1.w,
                    a2.x,a2.y,a2.z,a2.w, a3.x,a3.y,a3.z,a3.w};

    int ysIdx = ((b * LL + l0) * KK + k) * 192 + r * 32 + lane;
#pragma unroll 2
    for (int s = 0; s < TT; s++) {
        float4 c0 = sC[s * 4 + 0], c1 = sC[s * 4 + 1], c2 = sC[s * 4 + 2], c3 = sC[s * 4 + 3];
        float q0 = h0[0] * c0.x;
        q0 = fmaf(h0[1], c0.y, q0); q0 = fmaf(h0[2], c0.z, q0); q0 = fmaf(h0[3], c0.w, q0);
        float q1 = h0[4] * c1.x;
        q1 = fmaf(h0[5], c1.y, q1); q1 = fmaf(h0[6], c1.z, q1); q1 = fmaf(h0[7], c1.w, q1);
        float q2 = h0[8] * c2.x;
        q2 = fmaf(h0[9], c2.y, q2); q2 = fmaf(h0[10], c2.z, q2); q2 = fmaf(h0[11], c2.w, q2);
        float q3 = h0[12] * c3.x;
        q3 = fmaf(h0[13], c3.y, q3); q3 = fmaf(h0[14], c3.z, q3); q3 = fmaf(h0[15], c3.w, q3);
        d_ys[ysIdx] = fmaf(sP[r * TT + s], (q0 + q1) + (q2 + q3), d_ys[ysIdx]);
        ysIdx += KK * 192;
    }
}

// ---------- K5: cross-merge + LayerNorm + out-proj ----------
__global__ __launch_bounds__(192) void k5_out(const float* __restrict__ lng,
                                              const float* __restrict__ lnb,
                                              const float* __restrict__ wout,
                                              float* __restrict__ out) {
    __shared__ __align__(16) float sy[32 * DI];   // 24KB
    __shared__ float smu[32], srs[32];
    int t = threadIdx.x;  // 192
    int pb = blockIdx.x * 32;    // 32 | 4096: never crosses batch
    int b = pb >> 12;
    int lbase = pb & 4095;

    for (int p = 0; p < 32; p++) {
        int l = lbase + p;
        float v = 0.f;
#pragma unroll
        for (int k = 0; k < KK; k++) {
            int pos = sigma_k(k, l);
            v += d_ys[((b * LL + pos) * KK + k) * 192 + t];
        }
        sy[p * DI + t] = v;
    }
    __syncthreads();

    int warp = t >> 5, lane = t & 31;
    for (int p = warp; p < 32; p += 6) {
        float s1 = 0.f, s2 = 0.f;
#pragma unroll
        for (int j = 0; j < 6; j++) {
            float v = sy[p * DI + lane + j * 32];
            s1 += v; s2 = fmaf(v, v, s2);
        }
#pragma unroll
        for (int o = 16; o > 0; o >>= 1) {
            s1 += __shfl_down_sync(0xffffffffu, s1, o);
            s2 += __shfl_down_sync(0xffffffffu, s2, o);
        }
        if (lane == 0) {
            float mu = s1 * (1.f / DI);
            float var = s2 * (1.f / DI) - mu * mu;
            smu[p] = mu;
            srs[p] = rsqrtf(var + 1e-5f);
        }
    }
    __syncthreads();

    float g = lng[t], be = lnb[t];
    for (int p = 0; p < 32; p++)
        sy[p * DI + t] = (sy[p * DI + t] - smu[p]) * srs[p] * g + be;
    __syncthreads();

    const float4* sy4 = reinterpret_cast<const float4*>(sy);
    int row = t / 48;     // 0..3 -> pixels row*8 .. +7
    int col = t % 48;     // outputs 2col, 2col+1
    float a0[8], a1[8];
#pragma unroll
    for (int q = 0; q < 8; q++) { a0[q] = 0.f; a1[q] = 0.f; }
    for (int c4 = 0; c4 < DI / 4; c4++) {
        float2 w0 = *reinterpret_cast<const float2*>(&wout[(c4 * 4 + 0) * 96 + 2 * col]);
        float2 w1 = *reinterpret_cast<const float2*>(&wout[(c4 * 4 + 1) * 96 + 2 * col]);
        float2 w2 = *reinterpret_cast<const float2*>(&wout[(c4 * 4 + 2) * 96 + 2 * col]);
        float2 w3 = *reinterpret_cast<const float2*>(&wout[(c4 * 4 + 3) * 96 + 2 * col]);
#pragma unroll
        for (int q = 0; q < 8; q++) {
            float4 sv = sy4[(row * 8 + q) * (DI / 4) + c4];
            a0[q] = fmaf(sv.x, w0.x, a0[q]); a1[q] = fmaf(sv.x, w0.y, a1[q]);
            a0[q] = fmaf(sv.y, w1.x, a0[q]); a1[q] = fmaf(sv.y, w1.y, a1[q]);
            a0[q] = fmaf(sv.z, w2.x, a0[q]); a1[q] = fmaf(sv.z, w2.y, a1[q]);
            a0[q] = fmaf(sv.w, w3.x, a0[q]); a1[q] = fmaf(sv.w, w3.y, a1[q]);
        }
    }
#pragma unroll
    for (int q = 0; q < 8; q++) {
        float2 v = make_float2(a0[q], a1[q]);
        *reinterpret_cast<float2*>(&out[(pb + row * 8 + q) * 96 + 2 * col]) = v;
    }
}

extern "C" void kernel_launch(void* const* d_in, const int* in_sizes, int n_in,
                              void* d_out, int out_size) {
    const float* x    = (const float*)d_in[0];
    const float* w_in = (const float*)d_in[1];
    const float* wconv= (const float*)d_in[2];
    const float* bconv= (const float*)d_in[3];
    const float* xpw  = (const float*)d_in[4];
    const float* Alog = (const float*)d_in[5];
    const float* Ds   = (const float*)d_in[6];
    const float* dtb  = (const float*)d_in[7];
    const float* lng  = (const float*)d_in[8];
    const float* lnb  = (const float*)d_in[9];
    const float* wout = (const float*)d_in[10];
    float* out = (float*)d_out;

    cudaFuncSetAttribute(k1_mma, cudaFuncAttributeMaxDynamicSharedMemorySize, K1_SMEM_BYTES);
    cudaFuncSetAttribute(k3_mma, cudaFuncAttributeMaxDynamicSharedMemorySize, K3_SMEM_BYTES);

    k1_mma<<<BB * LL / 128, 256, K1_SMEM_BYTES>>>(x, w_in);
    k2_conv<<<BB * LL / 8, DI>>>(wconv, bconv);
    k3_mma<<<BB * LL / 128, 256, K3_SMEM_BYTES>>>(xpw, Alog, dtb);
    k4_scanA<<<BB * KK * NCH, 192>>>(Ds);
    k4_scanB<<<24, 256>>>();
    k4_scanC<<<BB * KK * NCH, 192>>>();
    k5_out<<<BB * LL / 32, 192>>>(lng, lnb, wout, out);
}